// round 3
// baseline (speedup 1.0000x reference)
#include <cuda_runtime.h>

// ---------------------------------------------------------------------------
// S5 layer:  B=8, L=4096, H=512, P=256
//   Lambda_bar = exp(Lambda*dt);  B_bar = (Lambda_bar-1)/Lambda * B_tilde
//   Bu[b,l,p]  = sum_h u[b,l,h] * B_bar[p,h]                  (complex)
//   x_k        = Lambda_bar * x_{k-1} + Bu_k   (scan over l)
//   out[b,l,h] = 2*Re( sum_p x[b,l,p]*C_tilde[h,p] ) + D[h]*u[b,l,h]
//   state[b,p] = x[b,L-1,p]
//
// Output 0 layout (verified round 1): out (8*4096*512 f32) at offset 0.
// Output 1 (state) layout determined at runtime from out_size:
//   state_floats == 2048 -> real part only (astype(float32) semantics)
//   state_floats == 4096 -> planar [real(8,256), imag(8,256)]
//   (interleaved (re,im) pairs disproven in round 1: rel_err ~ sqrt(2))
// ---------------------------------------------------------------------------

#define BDIM 8
#define LDIM 4096
#define HDIM 512
#define PDIM 256
#define BL   (BDIM * LDIM)      // 32768 rows
#define NCH  64                 // scan chunks per sequence
#define TCH  (LDIM / NCH)       // 64 steps per chunk
#define OUT_ELEMS ((size_t)BL * HDIM)   // 16777216

// -------------------- device scratch (no runtime allocation) ---------------
__device__ float2 g_Bu[(size_t)BL * PDIM];        // 64 MB: Bu, then xs in-place
__device__ float2 g_end[BDIM * NCH * PDIM];
__device__ float2 g_carry[BDIM * NCH * PDIM];
__device__ float  g_W1[HDIM * 2 * PDIM];          // [k=h][n=2p(+1)]
__device__ float  g_W2[2 * PDIM * HDIM];          // [k=2p(+1)][n=h]
__device__ float2 g_lambda[PDIM];
__device__ float2 g_f[PDIM];
__device__ float2 g_aT[PDIM];

// -------------------- f32x2 packed-FMA helpers (sm_103a) -------------------
typedef unsigned long long ull;

__device__ __forceinline__ ull pack2(float x, float y) {
    ull r; asm("mov.b64 %0, {%1, %2};" : "=l"(r) : "f"(x), "f"(y)); return r;
}
__device__ __forceinline__ ull fma2(ull a, ull b, ull c) {
    ull d; asm("fma.rn.f32x2 %0, %1, %2, %3;" : "=l"(d) : "l"(a), "l"(b), "l"(c)); return d;
}
__device__ __forceinline__ void unpack2(ull v, float& lo, float& hi) {
    asm("mov.b64 {%0, %1}, %2;" : "=f"(lo), "=f"(hi) : "l"(v));
}

__device__ __forceinline__ float2 cfma(float2 a, float2 x, float2 v) {
    // a*x + v (complex)
    float2 r;
    r.x = fmaf(a.x, x.x, fmaf(-a.y, x.y, v.x));
    r.y = fmaf(a.x, x.y, fmaf(a.y, x.x, v.y));
    return r;
}

// -------------------- setup: per-mode constants (fp64 for accuracy) --------
__global__ void k_setup_small(const float* __restrict__ Lre,
                              const float* __restrict__ Lim,
                              const float* __restrict__ lstep) {
    int p = threadIdx.x;
    if (p >= PDIM) return;
    double lr = (double)Lre[p];
    double li = (double)Lim[p];
    double dt = exp((double)lstep[p]);
    double mag = exp(lr * dt);
    double ang = li * dt;
    double lbr = mag * cos(ang);
    double lbi = mag * sin(ang);
    g_lambda[p] = make_float2((float)lbr, (float)lbi);
    // f = (lambda_bar - 1) / lambda
    double den = lr * lr + li * li;
    double nr = lbr - 1.0, ni = lbi;
    g_f[p] = make_float2((float)((nr * lr + ni * li) / den),
                         (float)((ni * lr - nr * li) / den));
    // a^T (chunk-advance factor)
    double magT = exp(lr * dt * (double)TCH);
    double angT = li * dt * (double)TCH;
    g_aT[p] = make_float2((float)(magT * cos(angT)), (float)(magT * sin(angT)));
}

// -------------------- setup: W1 (input proj) and W2 (output proj) ----------
__global__ void k_setup_weights(const float* __restrict__ Bw,   // (P,H,2)
                                const float* __restrict__ Cw) { // (H,P,2)
    int idx = blockIdx.x * 256 + threadIdx.x;   // 0 .. 262143
    // W1[h][n] : n=2p -> Re(f_p * B~[p,h]),  n=2p+1 -> Im(...)
    {
        int h = idx >> 9, n = idx & 511, p = n >> 1;
        float2 f = g_f[p];
        float b0 = Bw[p * (HDIM * 2) + h * 2 + 0];
        float b1 = Bw[p * (HDIM * 2) + h * 2 + 1];
        g_W1[idx] = (n & 1) ? (f.x * b1 + f.y * b0) : (f.x * b0 - f.y * b1);
    }
    // W2[k][h] : k=2p -> 2*C_re[h,p],  k=2p+1 -> -2*C_im[h,p]
    {
        int k = idx >> 9, h = idx & 511, p = k >> 1;
        float c0 = Cw[h * (PDIM * 2) + p * 2 + 0];
        float c1 = Cw[h * (PDIM * 2) + p * 2 + 1];
        g_W2[idx] = (k & 1) ? (-2.0f * c1) : (2.0f * c0);
    }
}

// -------------------- GEMM: 128x128x16 tile, 8x8/thread, f32x2 FMAs --------
// C(M=32768, N=512) = A(M,512) * W(512,512); EPI=0: Out->g_Bu, W=g_W1
//                                            EPI=1: A=g_Bu, W=g_W2, +D*u
template <int EPI>
__global__ __launch_bounds__(256, 2)
void k_gemm512(const float* __restrict__ Aext,
               float* __restrict__ Outext,
               const float* __restrict__ U,
               const float* __restrict__ Dv) {
    const float* A   = (EPI == 0) ? Aext : (const float*)g_Bu;
    const float* W   = (EPI == 0) ? g_W1 : g_W2;
    float*       Out = (EPI == 0) ? (float*)g_Bu : Outext;

    __shared__ __align__(16) float As[16][128];
    __shared__ __align__(16) float Bs[16][128];

    const int tid     = threadIdx.x;
    const int nBase   = blockIdx.x * 128;
    const int rowBase = blockIdx.y * 128;
    const int tRow    = tid >> 4;     // 0..15
    const int tCol    = tid & 15;     // 0..15

    ull acc[8][4];
#pragma unroll
    for (int i = 0; i < 8; i++)
#pragma unroll
        for (int j = 0; j < 4; j++) acc[i][j] = 0ULL;

    const int aM0 = tid >> 2;         // 0..63
    const int aK0 = (tid & 3) * 4;    // 0,4,8,12
    const int bK0 = tid >> 5;         // 0..7
    const int bN0 = (tid & 31) * 4;   // 0..124

    for (int k0 = 0; k0 < 512; k0 += 16) {
#pragma unroll
        for (int i = 0; i < 2; i++) {
            int m = aM0 + i * 64;
            float4 v = *(const float4*)(A + (size_t)(rowBase + m) * 512 + k0 + aK0);
            As[aK0 + 0][m] = v.x; As[aK0 + 1][m] = v.y;
            As[aK0 + 2][m] = v.z; As[aK0 + 3][m] = v.w;
        }
#pragma unroll
        for (int i = 0; i < 2; i++) {
            int k = bK0 + i * 8;
            *(float4*)&Bs[k][bN0] = *(const float4*)(W + (size_t)(k0 + k) * 512 + nBase + bN0);
        }
        __syncthreads();
#pragma unroll
        for (int k = 0; k < 16; k++) {
            float4 a0 = *(float4*)&As[k][tRow * 8];
            float4 a1 = *(float4*)&As[k][tRow * 8 + 4];
            const ull* bp = (const ull*)&Bs[k][tCol * 8];
            ull b0 = bp[0], b1 = bp[1], b2 = bp[2], b3 = bp[3];
            float af[8] = {a0.x, a0.y, a0.z, a0.w, a1.x, a1.y, a1.z, a1.w};
#pragma unroll
            for (int i = 0; i < 8; i++) {
                ull av = pack2(af[i], af[i]);
                acc[i][0] = fma2(av, b0, acc[i][0]);
                acc[i][1] = fma2(av, b1, acc[i][1]);
                acc[i][2] = fma2(av, b2, acc[i][2]);
                acc[i][3] = fma2(av, b3, acc[i][3]);
            }
        }
        __syncthreads();
    }

    const int col0 = nBase + tCol * 8;
    if (EPI == 0) {
#pragma unroll
        for (int i = 0; i < 8; i++) {
            int row = rowBase + tRow * 8 + i;
            float4 o0, o1;
            unpack2(acc[i][0], o0.x, o0.y); unpack2(acc[i][1], o0.z, o0.w);
            unpack2(acc[i][2], o1.x, o1.y); unpack2(acc[i][3], o1.z, o1.w);
            float4* dst = (float4*)(Out + (size_t)row * 512 + col0);
            dst[0] = o0; dst[1] = o1;
        }
    } else {
        float d[8];
#pragma unroll
        for (int j = 0; j < 8; j++) d[j] = Dv[col0 + j];
#pragma unroll
        for (int i = 0; i < 8; i++) {
            int row = rowBase + tRow * 8 + i;
            float4 o0, o1;
            unpack2(acc[i][0], o0.x, o0.y); unpack2(acc[i][1], o0.z, o0.w);
            unpack2(acc[i][2], o1.x, o1.y); unpack2(acc[i][3], o1.z, o1.w);
            const float4* up = (const float4*)(U + (size_t)row * 512 + col0);
            float4 u0 = up[0], u1 = up[1];
            o0.x = fmaf(d[0], u0.x, o0.x); o0.y = fmaf(d[1], u0.y, o0.y);
            o0.z = fmaf(d[2], u0.z, o0.z); o0.w = fmaf(d[3], u0.w, o0.w);
            o1.x = fmaf(d[4], u1.x, o1.x); o1.y = fmaf(d[5], u1.y, o1.y);
            o1.z = fmaf(d[6], u1.z, o1.z); o1.w = fmaf(d[7], u1.w, o1.w);
            float4* dst = (float4*)(Out + (size_t)row * 512 + col0);
            dst[0] = o0; dst[1] = o1;
        }
    }
}

// -------------------- scan phase A: chunk-local end values -----------------
__global__ void k_scan_end() {
    int g = blockIdx.x * 256 + threadIdx.x;           // 131072 threads
    int p = g & (PDIM - 1);
    int c = (g >> 8) & (NCH - 1);
    int b = g >> 14;
    float2 a = g_lambda[p];
    float2 e = make_float2(0.0f, 0.0f);
    const float2* src = g_Bu + ((size_t)(b * LDIM + c * TCH)) * PDIM + p;
#pragma unroll 4
    for (int j = 0; j < TCH; j++) e = cfma(a, e, src[(size_t)j * PDIM]);
    g_end[(b * NCH + c) * PDIM + p] = e;
}

// -------------------- scan phase B: cross-chunk carries --------------------
__global__ void k_scan_carry() {
    int g = blockIdx.x * 256 + threadIdx.x;           // 2048 threads
    int p = g & (PDIM - 1);
    int b = g >> 8;
    float2 aT = g_aT[p];
    float2 carry = make_float2(0.0f, 0.0f);
    for (int c = 0; c < NCH; c++) {
        g_carry[(b * NCH + c) * PDIM + p] = carry;
        float2 e = g_end[(b * NCH + c) * PDIM + p];
        carry = cfma(aT, carry, e);
    }
}

// -------------------- scan phase C: rescan with carry, write xs + state ----
// STATE_MODE 0: real-only   (state region = 2048 floats)
// STATE_MODE 1: planar      (state region = 4096 floats: re block, im block)
template <int STATE_MODE>
__global__ void k_scan_write(float* __restrict__ out_state) {
    int g = blockIdx.x * 256 + threadIdx.x;           // 131072 threads
    int p = g & (PDIM - 1);
    int c = (g >> 8) & (NCH - 1);
    int b = g >> 14;
    float2 a = g_lambda[p];
    float2 x = g_carry[(b * NCH + c) * PDIM + p];
    float2* buf = g_Bu + ((size_t)(b * LDIM + c * TCH)) * PDIM + p;
#pragma unroll 4
    for (int j = 0; j < TCH; j++) {
        x = cfma(a, x, buf[(size_t)j * PDIM]);
        buf[(size_t)j * PDIM] = x;                    // xs in-place
    }
    if (c == NCH - 1) {
        if (STATE_MODE == 0) {
            out_state[b * PDIM + p] = x.x;            // real part only
        } else {
            out_state[b * PDIM + p] = x.x;            // real plane
            out_state[BDIM * PDIM + b * PDIM + p] = x.y;  // imag plane
        }
    }
}

// ---------------------------------------------------------------------------
extern "C" void kernel_launch(void* const* d_in, const int* in_sizes, int n_in,
                              void* d_out, int out_size) {
    const float* u    = (const float*)d_in[0];   // (8,4096,512)
    const float* Lre  = (const float*)d_in[1];   // (256,)
    const float* Lim  = (const float*)d_in[2];   // (256,)
    const float* Bw   = (const float*)d_in[3];   // (256,512,2)
    const float* Cw   = (const float*)d_in[4];   // (512,256,2)
    const float* Dv   = (const float*)d_in[5];   // (512,)
    const float* lst  = (const float*)d_in[6];   // (256,)
    float* out = (float*)d_out;
    float* out_state = out + OUT_ELEMS;          // after (8,4096,512)

    // Disambiguate state layout from the actual buffer size.
    const long long state_floats = (long long)out_size - (long long)OUT_ELEMS;

    (void)in_sizes; (void)n_in;

    k_setup_small<<<1, 256>>>(Lre, Lim, lst);
    k_setup_weights<<<1024, 256>>>(Bw, Cw);

    dim3 ggrid(HDIM / 128, BL / 128);   // (4, 256)
    k_gemm512<0><<<ggrid, 256>>>(u, nullptr, nullptr, nullptr);

    k_scan_end<<<(BDIM * NCH * PDIM) / 256, 256>>>();
    k_scan_carry<<<(BDIM * PDIM) / 256, 256>>>();
    if (state_floats == BDIM * PDIM) {
        // 2048 floats: real part only (complex64 -> float32 astype semantics)
        k_scan_write<0><<<(BDIM * NCH * PDIM) / 256, 256>>>(out_state);
    } else {
        // 4096 floats: planar [real(8,256), imag(8,256)]
        k_scan_write<1><<<(BDIM * NCH * PDIM) / 256, 256>>>(out_state);
    }

    k_gemm512<1><<<ggrid, 256>>>(nullptr, out, u, Dv);
}

// round 9
// speedup vs baseline: 2.2304x; 2.2304x over previous
#include <cuda_runtime.h>
#include <cuda_bf16.h>
#include <cstdint>

// ---------------------------------------------------------------------------
// S5 layer:  B=8, L=4096, H=512, P=256
// Tensor path: warp-level mma.sync bf16 (HMMA) — tcgen05 PTX is rejected by
// this build's ptxas (.target sm_103, no 'a' feature), so we use the legacy
// tensor-core path which compiles on plain sm_103.
//
//   GEMM1: Bu[token][n=2p|2p+1] = u[token][h] @ W1T[n][h]^T
//   scan:  chunked diagonal complex recurrence (verified fp32 path)
//   GEMM2: out = xs_real_view @ W2T^T + D*u
// Precision: fp32 x = x_hi + x_lo (bf16 each);  A@B ~= Ahi@Bhi+Alo@Bhi+Ahi@Blo
// ---------------------------------------------------------------------------

#define BDIM 8
#define LDIM 4096
#define HDIM 512
#define PDIM 256
#define BL   (BDIM * LDIM)          // 32768 tokens
#define NCH  64
#define TCH  (LDIM / NCH)           // 64
#define OUT_ELEMS ((size_t)BL * HDIM)

// -------------------- device scratch ---------------------------------------
__device__ float2 g_Bu[(size_t)BL * PDIM];          // 64 MB (Bu f32)
__device__ float2 g_end[BDIM * NCH * PDIM];
__device__ float2 g_carry[BDIM * NCH * PDIM];
__device__ __nv_bfloat16 g_Ahi[(size_t)BL * 512];   // u split hi
__device__ __nv_bfloat16 g_Alo[(size_t)BL * 512];   // u split lo
__device__ __nv_bfloat16 g_Xhi[(size_t)BL * 512];   // xs split hi (real view)
__device__ __nv_bfloat16 g_Xlo[(size_t)BL * 512];
__device__ __nv_bfloat16 g_W1Thi[512 * 512];        // [n][k=h]
__device__ __nv_bfloat16 g_W1Tlo[512 * 512];
__device__ __nv_bfloat16 g_W2Thi[512 * 512];        // [h][k=2p|2p+1]
__device__ __nv_bfloat16 g_W2Tlo[512 * 512];
__device__ float2 g_lambda[PDIM];
__device__ float2 g_f[PDIM];
__device__ float2 g_aT[PDIM];

// -------------------- PTX helpers ------------------------------------------
__device__ __forceinline__ uint32_t smem_u32(const void* p) {
    uint32_t a;
    asm("{ .reg .u64 t; cvta.to.shared.u64 t, %1; cvt.u32.u64 %0, t; }"
        : "=r"(a) : "l"(p));
    return a;
}
__device__ __forceinline__ void cp16(uint32_t saddr, const void* gptr) {
    uint64_t g;
    asm("cvta.to.global.u64 %0, %1;" : "=l"(g) : "l"(gptr));
    asm volatile("cp.async.cg.shared.global [%0], [%1], 16;"
                 :: "r"(saddr), "l"(g) : "memory");
}
__device__ __forceinline__ void cp_commit() {
    asm volatile("cp.async.commit_group;" ::: "memory");
}
template <int N>
__device__ __forceinline__ void cp_wait() {
    asm volatile("cp.async.wait_group %0;" :: "n"(N) : "memory");
}
__device__ __forceinline__ void ldm_x4(uint32_t* r, uint32_t addr) {
    asm volatile("ldmatrix.sync.aligned.m8n8.x4.shared.b16 {%0,%1,%2,%3}, [%4];"
                 : "=r"(r[0]), "=r"(r[1]), "=r"(r[2]), "=r"(r[3]) : "r"(addr));
}
__device__ __forceinline__ void mma16816(float* c, const uint32_t* a, const uint32_t* b) {
    asm volatile(
        "mma.sync.aligned.m16n8k16.row.col.f32.bf16.bf16.f32 "
        "{%0,%1,%2,%3}, {%4,%5,%6,%7}, {%8,%9}, {%0,%1,%2,%3};"
        : "+f"(c[0]), "+f"(c[1]), "+f"(c[2]), "+f"(c[3])
        : "r"(a[0]), "r"(a[1]), "r"(a[2]), "r"(a[3]), "r"(b[0]), "r"(b[1]));
}
__device__ __forceinline__ uint32_t sw128(uint32_t bo) {
    return bo ^ ((bo >> 3) & 0x70);
}

// -------------------- math helpers -----------------------------------------
__device__ __forceinline__ float2 cfma(float2 a, float2 x, float2 v) {
    float2 r;
    r.x = fmaf(a.x, x.x, fmaf(-a.y, x.y, v.x));
    r.y = fmaf(a.x, x.y, fmaf(a.y, x.x, v.y));
    return r;
}

// -------------------- setup kernels ----------------------------------------
__global__ void k_setup_small(const float* __restrict__ Lre,
                              const float* __restrict__ Lim,
                              const float* __restrict__ lstep) {
    int p = threadIdx.x;
    if (p >= PDIM) return;
    double lr = (double)Lre[p], li = (double)Lim[p];
    double dt = exp((double)lstep[p]);
    double mag = exp(lr * dt), ang = li * dt;
    double lbr = mag * cos(ang), lbi = mag * sin(ang);
    g_lambda[p] = make_float2((float)lbr, (float)lbi);
    double den = lr * lr + li * li;
    double nr = lbr - 1.0, ni = lbi;
    g_f[p] = make_float2((float)((nr * lr + ni * li) / den),
                         (float)((ni * lr - nr * li) / den));
    double magT = exp(lr * dt * (double)TCH);
    double angT = li * dt * (double)TCH;
    g_aT[p] = make_float2((float)(magT * cos(angT)), (float)(magT * sin(angT)));
}

__global__ void k_setup_weights(const float* __restrict__ Bw,   // (P,H,2)
                                const float* __restrict__ Cw) { // (H,P,2)
    int idx = blockIdx.x * 256 + threadIdx.x;   // 0..262143
    // W1T[n][h] = (n odd) ? Im(f_p * B~[p,h]) : Re(f_p * B~[p,h]),  p=n/2
    {
        int n = idx >> 9, h = idx & 511, p = n >> 1;
        float2 f = g_f[p];
        float b0 = Bw[p * 1024 + h * 2 + 0];
        float b1 = Bw[p * 1024 + h * 2 + 1];
        float w = (n & 1) ? (f.x * b1 + f.y * b0) : (f.x * b0 - f.y * b1);
        __nv_bfloat16 hi = __float2bfloat16(w);
        g_W1Thi[idx] = hi;
        g_W1Tlo[idx] = __float2bfloat16(w - __bfloat162float(hi));
    }
    // W2T[h][k] : k=2p -> 2*C_re[h,p],  k=2p+1 -> -2*C_im[h,p]
    {
        int h = idx >> 9, k = idx & 511, p = k >> 1;
        float c0 = Cw[h * 512 + p * 2 + 0];
        float c1 = Cw[h * 512 + p * 2 + 1];
        float w = (k & 1) ? (-2.0f * c1) : (2.0f * c0);
        __nv_bfloat16 hi = __float2bfloat16(w);
        g_W2Thi[idx] = hi;
        g_W2Tlo[idx] = __float2bfloat16(w - __bfloat162float(hi));
    }
}

__global__ void k_split_u(const float* __restrict__ u) {
    size_t i = (size_t)blockIdx.x * 256 + threadIdx.x;   // x4 floats each
    float4 v = ((const float4*)u)[i];
    __nv_bfloat16 h0 = __float2bfloat16(v.x), h1 = __float2bfloat16(v.y);
    __nv_bfloat16 h2 = __float2bfloat16(v.z), h3 = __float2bfloat16(v.w);
    __nv_bfloat162 a01, a23;
    a01.x = h0; a01.y = h1; a23.x = h2; a23.y = h3;
    ((__nv_bfloat162*)g_Ahi)[2 * i + 0] = a01;
    ((__nv_bfloat162*)g_Ahi)[2 * i + 1] = a23;
    __nv_bfloat162 l01, l23;
    l01.x = __float2bfloat16(v.x - __bfloat162float(h0));
    l01.y = __float2bfloat16(v.y - __bfloat162float(h1));
    l23.x = __float2bfloat16(v.z - __bfloat162float(h2));
    l23.y = __float2bfloat16(v.w - __bfloat162float(h3));
    ((__nv_bfloat162*)g_Alo)[2 * i + 0] = l01;
    ((__nv_bfloat162*)g_Alo)[2 * i + 1] = l23;
}

// -------------------- mma.sync GEMM ----------------------------------------
// CTA tile 128(M) x 128(N); 8 warps in 4(M) x 2(N); warp tile 32 x 64.
// K streamed in 64-elem chunks; smem per stage: Ahi|Alo|Bhi|Blo = 4 x 16KB.
// Double-buffered via cp.async groups. SW128 swizzle; ldmatrix fragments.
#define KCHN       64
#define NCHUNK     8
#define OP_BYTES   16384
#define STAGE_BYTES 65536
#define GEMM_SMEM  (2 * STAGE_BYTES)

template <int EPI>
__global__ __launch_bounds__(256, 1)
void k_mma_gemm(float* __restrict__ OutExt,
                const float* __restrict__ U,
                const float* __restrict__ Dv) {
    const __nv_bfloat16* Ahi = EPI ? g_Xhi : g_Ahi;
    const __nv_bfloat16* Alo = EPI ? g_Xlo : g_Alo;
    const __nv_bfloat16* Bhi = EPI ? g_W2Thi : g_W1Thi;
    const __nv_bfloat16* Blo = EPI ? g_W2Tlo : g_W1Tlo;
    float* Out = EPI ? OutExt : (float*)g_Bu;

    extern __shared__ char smem[];
    const uint32_t sbase = smem_u32(smem);
    const int tid = threadIdx.x;
    const int wid = tid >> 5, lane = tid & 31;
    const int warpM = wid & 3, warpN = wid >> 2;
    const int mBase = blockIdx.y * 128;
    const int nBase = blockIdx.x * 128;

    float acc[2][8][4];
#pragma unroll
    for (int mt = 0; mt < 2; mt++)
#pragma unroll
        for (int nt = 0; nt < 8; nt++)
#pragma unroll
            for (int j = 0; j < 4; j++) acc[mt][nt][j] = 0.0f;

    // ---- async load of one K-chunk into a stage ----
    auto load_stage = [&](int stg, int c) {
        uint32_t sb = sbase + stg * STAGE_BYTES;
#pragma unroll
        for (int op = 0; op < 4; op++) {
            const char* g =
                (op == 0) ? (const char*)Ahi :
                (op == 1) ? (const char*)Alo :
                (op == 2) ? (const char*)Bhi : (const char*)Blo;
            const int rb = (op < 2) ? mBase : nBase;
            const char* gbase = g + (size_t)rb * 1024 + (size_t)c * 128;
#pragma unroll
            for (int i = 0; i < 4; i++) {
                int idx = tid + i * 256;          // 0..1023
                int r = idx >> 3, q = idx & 7;
                uint32_t bo = (uint32_t)(r * 128 + q * 16);
                cp16(sb + op * OP_BYTES + sw128(bo),
                     gbase + (size_t)r * 1024 + q * 16);
            }
        }
    };

    load_stage(0, 0);
    cp_commit();

    // fragment-address components (constant per thread)
    const int rowA = ((lane >> 3) & 1) * 8 + (lane & 7);
    const int khA  = lane >> 4;                // 0/1 -> k-half
    const int rowB = ((lane >> 4) & 1) * 8 + (lane & 7);
    const int khB  = (lane >> 3) & 1;

    for (int c = 0; c < NCHUNK; c++) {
        if (c + 1 < NCHUNK) {
            load_stage((c + 1) & 1, c + 1);
            cp_commit();
            cp_wait<1>();
        } else {
            cp_wait<0>();
        }
        __syncthreads();

        uint32_t sb = sbase + (c & 1) * STAGE_BYTES;
#pragma unroll
        for (int k16 = 0; k16 < 4; k16++) {
            uint32_t ah[2][4], al[2][4];
#pragma unroll
            for (int mt = 0; mt < 2; mt++) {
                int m0 = warpM * 32 + mt * 16;
                uint32_t bo = (uint32_t)((m0 + rowA) * 128 + k16 * 32 + khA * 16);
                uint32_t sw = sw128(bo);
                ldm_x4(ah[mt], sb + 0 * OP_BYTES + sw);
                ldm_x4(al[mt], sb + 1 * OP_BYTES + sw);
            }
#pragma unroll
            for (int np = 0; np < 4; np++) {
                int n0 = warpN * 64 + np * 16;
                uint32_t bo = (uint32_t)((n0 + rowB) * 128 + k16 * 32 + khB * 16);
                uint32_t sw = sw128(bo);
                uint32_t bh[4], bl[4];
                ldm_x4(bh, sb + 2 * OP_BYTES + sw);
                ldm_x4(bl, sb + 3 * OP_BYTES + sw);
#pragma unroll
                for (int j = 0; j < 2; j++) {
                    int nt = np * 2 + j;
#pragma unroll
                    for (int mt = 0; mt < 2; mt++) {
                        mma16816(acc[mt][nt], ah[mt], &bh[2 * j]);
                        mma16816(acc[mt][nt], al[mt], &bh[2 * j]);
                        mma16816(acc[mt][nt], ah[mt], &bl[2 * j]);
                    }
                }
            }
        }
        __syncthreads();
    }

    // ---- epilogue: acc fragment -> gmem ----
    const int r0  = mBase + warpM * 32 + (lane >> 2);
    const int c00 = nBase + warpN * 64 + 2 * (lane & 3);
#pragma unroll
    for (int mt = 0; mt < 2; mt++) {
#pragma unroll
        for (int nt = 0; nt < 8; nt++) {
            int row = r0 + mt * 16;
            int col = c00 + nt * 8;
            float2 v0 = make_float2(acc[mt][nt][0], acc[mt][nt][1]);
            float2 v1 = make_float2(acc[mt][nt][2], acc[mt][nt][3]);
            if (EPI) {
                float2 dv = *(const float2*)(Dv + col);
                float2 u0 = *(const float2*)(U + (size_t)row * 512 + col);
                float2 u1 = *(const float2*)(U + (size_t)(row + 8) * 512 + col);
                v0.x = fmaf(dv.x, u0.x, v0.x); v0.y = fmaf(dv.y, u0.y, v0.y);
                v1.x = fmaf(dv.x, u1.x, v1.x); v1.y = fmaf(dv.y, u1.y, v1.y);
            }
            *(float2*)(Out + (size_t)row * 512 + col) = v0;
            *(float2*)(Out + (size_t)(row + 8) * 512 + col) = v1;
        }
    }
}

// -------------------- scan (verified fp32 path) ----------------------------
__global__ void k_scan_end() {
    int g = blockIdx.x * 256 + threadIdx.x;
    int p = g & (PDIM - 1);
    int c = (g >> 8) & (NCH - 1);
    int b = g >> 14;
    float2 a = g_lambda[p];
    float2 e = make_float2(0.0f, 0.0f);
    const float2* src = g_Bu + ((size_t)(b * LDIM + c * TCH)) * PDIM + p;
#pragma unroll 4
    for (int j = 0; j < TCH; j++) e = cfma(a, e, src[(size_t)j * PDIM]);
    g_end[(b * NCH + c) * PDIM + p] = e;
}

__global__ void k_scan_carry() {
    int g = blockIdx.x * 256 + threadIdx.x;
    int p = g & (PDIM - 1);
    int b = g >> 8;
    float2 aT = g_aT[p];
    float2 carry = make_float2(0.0f, 0.0f);
    for (int c = 0; c < NCH; c++) {
        g_carry[(b * NCH + c) * PDIM + p] = carry;
        float2 e = g_end[(b * NCH + c) * PDIM + p];
        carry = cfma(aT, carry, e);
    }
}

// phase C: rescan with carry; emit xs as bf16 hi/lo splits + state
template <int STATE_MODE>
__global__ void k_scan_write(float* __restrict__ out_state) {
    int g = blockIdx.x * 256 + threadIdx.x;
    int p = g & (PDIM - 1);
    int c = (g >> 8) & (NCH - 1);
    int b = g >> 14;
    float2 a = g_lambda[p];
    float2 x = g_carry[(b * NCH + c) * PDIM + p];
    const size_t base = ((size_t)(b * LDIM + c * TCH)) * PDIM + p;
    const float2* buf = g_Bu + base;
    __nv_bfloat162* xh = (__nv_bfloat162*)g_Xhi + base;
    __nv_bfloat162* xl = (__nv_bfloat162*)g_Xlo + base;
#pragma unroll 4
    for (int j = 0; j < TCH; j++) {
        x = cfma(a, x, buf[(size_t)j * PDIM]);
        __nv_bfloat16 hr = __float2bfloat16(x.x);
        __nv_bfloat16 hi = __float2bfloat16(x.y);
        __nv_bfloat162 h; h.x = hr; h.y = hi;
        xh[(size_t)j * PDIM] = h;
        __nv_bfloat162 l;
        l.x = __float2bfloat16(x.x - __bfloat162float(hr));
        l.y = __float2bfloat16(x.y - __bfloat162float(hi));
        xl[(size_t)j * PDIM] = l;
    }
    if (c == NCH - 1) {
        if (STATE_MODE == 0) {
            out_state[b * PDIM + p] = x.x;
        } else {
            out_state[b * PDIM + p] = x.x;
            out_state[BDIM * PDIM + b * PDIM + p] = x.y;
        }
    }
}

// ---------------------------------------------------------------------------
extern "C" void kernel_launch(void* const* d_in, const int* in_sizes, int n_in,
                              void* d_out, int out_size) {
    const float* u   = (const float*)d_in[0];
    const float* Lre = (const float*)d_in[1];
    const float* Lim = (const float*)d_in[2];
    const float* Bw  = (const float*)d_in[3];
    const float* Cw  = (const float*)d_in[4];
    const float* Dv  = (const float*)d_in[5];
    const float* lst = (const float*)d_in[6];
    float* out = (float*)d_out;
    float* out_state = out + OUT_ELEMS;
    const long long state_floats = (long long)out_size - (long long)OUT_ELEMS;
    (void)in_sizes; (void)n_in;

    cudaFuncSetAttribute(k_mma_gemm<0>, cudaFuncAttributeMaxDynamicSharedMemorySize, GEMM_SMEM);
    cudaFuncSetAttribute(k_mma_gemm<1>, cudaFuncAttributeMaxDynamicSharedMemorySize, GEMM_SMEM);

    k_setup_small<<<1, 256>>>(Lre, Lim, lst);
    k_setup_weights<<<1024, 256>>>(Bw, Cw);
    k_split_u<<<16384, 256>>>(u);

    dim3 ggrid(4, BL / 128);   // (N tiles, M tiles) = (4, 256)
    k_mma_gemm<0><<<ggrid, 256, GEMM_SMEM>>>(nullptr, nullptr, nullptr);

    k_scan_end<<<(BDIM * NCH * PDIM) / 256, 256>>>();
    k_scan_carry<<<(BDIM * PDIM) / 256, 256>>>();
    if (state_floats == BDIM * PDIM) {
        k_scan_write<0><<<(BDIM * NCH * PDIM) / 256, 256>>>(out_state);
    } else {
        k_scan_write<1><<<(BDIM * NCH * PDIM) / 256, 256>>>(out_state);
    }

    k_mma_gemm<1><<<ggrid, 256, GEMM_SMEM>>>(out, u, Dv);
}